// round 3
// baseline (speedup 1.0000x reference)
#include <cuda_runtime.h>
#include <cuda_fp16.h>
#include <cstdint>

#define NUM_CODES 100000
#define DIM 64
#define NVISITS 65536
#define LCODES 48

// fp16 pre-scaled tangent table + one trailing ZERO row (index NUM_CODES) for
// masked slots. Row = 64 halfs = 128 B = one L2 line. ~12.8 MB, L2-resident.
__device__ __align__(16) __half2 g_tang[(size_t)(NUM_CODES + 1) * (DIM / 2)];

// ---------------------------------------------------------------------------
// Pass 1: tang[c] = (atanh(min(||emb_c||,1-1e-7)) / max(||emb_c||,1e-15)) * emb_c
// One warp per row; lane owns 2 dims. Butterfly norm reduce, Taylor atanh(x)/x
// in the small-norm regime (data: ||x|| ~ 0.008). Warp NUM_CODES zeroes the pad row.
// ---------------------------------------------------------------------------
__global__ void __launch_bounds__(256) build_tangents(const float* __restrict__ emb) {
    int warp = (blockIdx.x * blockDim.x + threadIdx.x) >> 5;
    int lane = threadIdx.x & 31;
    if (warp > NUM_CODES) return;

    if (warp == NUM_CODES) {                     // zero row for masked ids
        g_tang[(size_t)warp * (DIM / 2) + lane] = __half2half2(__ushort_as_half(0));
        return;
    }

    const float2 v = reinterpret_cast<const float2*>(emb + (size_t)warp * DIM)[lane];
    float ss = v.x * v.x + v.y * v.y;
    #pragma unroll
    for (int o = 16; o; o >>= 1)
        ss += __shfl_xor_sync(0xffffffffu, ss, o);

    float s;
    if (ss < 0.09f) {
        // atanh(x)/x = 1 + y/3 + y^2/5 + y^3/7 + y^4/9, y = x^2 = ss.
        s = 1.0f + ss * (0.33333334f + ss * (0.2f + ss * (0.14285715f + ss * 0.11111111f)));
    } else {
        float n = fmaxf(sqrtf(ss), 1e-15f);
        float a = fminf(n, 1.0f - 1e-7f);
        s = atanhf(a) / n;
    }

    g_tang[(size_t)warp * (DIM / 2) + lane] =
        __float22half2_rn(make_float2(s * v.x, s * v.y));
}

// Convert one half2 and accumulate into a packed f32x2 accumulator:
// 2x F2F + 1x FADD2 (vs 2 CVT + 2 FADD scalar).
__device__ __forceinline__ void hacc2(uint32_t h2, unsigned long long& acc) {
    asm("{\n\t"
        ".reg .f16 l, h;\n\t"
        ".reg .f32 fl, fh;\n\t"
        ".reg .b64 fv;\n\t"
        "mov.b32 {l, h}, %1;\n\t"
        "cvt.f32.f16 fl, l;\n\t"
        "cvt.f32.f16 fh, h;\n\t"
        "mov.b64 fv, {fl, fh};\n\t"
        "add.rn.f32x2 %0, %0, fv;\n\t"
        "}" : "+l"(acc) : "r"(h2));
}

// ---------------------------------------------------------------------------
// Pass 2: out[visit] = mean over valid codes of tang[code].
// One warp per visit. Quarter-warp (8 lanes x 16B) per fp16 row -> one
// warp-wide LDG.128 gathers FOUR rows; 48 codes -> 12 loads, ALL issued
// up-front (max MLP), then consumed with packed f32x2 adds. Masked slots load
// the hot zero row (branchless); valid count via ballot+popc.
// ---------------------------------------------------------------------------
__global__ void __launch_bounds__(256, 3) visit_mean(const int* __restrict__ ids,
                                                     float* __restrict__ out) {
    int warp = (blockIdx.x * blockDim.x + threadIdx.x) >> 5;
    int lane = threadIdx.x & 31;
    if (warp >= NVISITS) return;

    const int quarter = lane >> 3;   // code slot within each group of 4
    const int ql      = lane & 7;    // 16B chunk within row: dims [8ql, 8ql+8)

    const int* __restrict__ vid = ids + (size_t)warp * LCODES;
    const int idA = __ldg(vid + lane);               // slots 0..31
    const int idB = __ldg(vid + 32 + (lane & 15));   // slots 32..47 (dup hi half)

    const int cnt = __popc(__ballot_sync(0xffffffffu, idA >= 0)) +
                    __popc(__ballot_sync(0xffffffffu, idB >= 0) & 0xffffu);

    const char* __restrict__ base = reinterpret_cast<const char*>(g_tang);

    // Issue all 12 gathers before consuming any (deep MLP).
    uint4 v[12];
    #pragma unroll
    for (int t = 0; t < 12; t++) {
        int slot = 4 * t + quarter;
        int id = (t < 8) ? __shfl_sync(0xffffffffu, idA, slot)
                         : __shfl_sync(0xffffffffu, idB, slot - 32);
        unsigned idx = (id >= 0) ? (unsigned)id : (unsigned)NUM_CODES;
        v[t] = *reinterpret_cast<const uint4*>(base + (size_t)idx * 128u + ql * 16);
    }

    unsigned long long acc[4] = {0ull, 0ull, 0ull, 0ull};
    #pragma unroll
    for (int t = 0; t < 12; t++) {
        hacc2(v[t].x, acc[0]);
        hacc2(v[t].y, acc[1]);
        hacc2(v[t].z, acc[2]);
        hacc2(v[t].w, acc[3]);
    }

    // Unpack packed accumulators and combine the four quarter-warps.
    float f[8];
    #pragma unroll
    for (int j = 0; j < 4; j++) {
        f[2 * j]     = __uint_as_float((unsigned)(acc[j] & 0xffffffffull));
        f[2 * j + 1] = __uint_as_float((unsigned)(acc[j] >> 32));
    }
    #pragma unroll
    for (int o = 16; o >= 8; o >>= 1) {
        #pragma unroll
        for (int i = 0; i < 8; i++)
            f[i] += __shfl_down_sync(0xffffffffu, f[i], o);
    }

    if (quarter == 0) {
        float inv = 1.0f / (float)(cnt > 1 ? cnt : 1);
        float4 o0 = make_float4(f[0] * inv, f[1] * inv, f[2] * inv, f[3] * inv);
        float4 o1 = make_float4(f[4] * inv, f[5] * inv, f[6] * inv, f[7] * inv);
        float4* op = reinterpret_cast<float4*>(out + (size_t)warp * DIM + ql * 8);
        op[0] = o0;
        op[1] = o1;
    }
}

extern "C" void kernel_launch(void* const* d_in, const int* in_sizes, int n_in,
                              void* d_out, int out_size) {
    const int*   code_ids = (const int*)d_in[0];   // [N, L] int32, -1 = pad
    const float* emb      = (const float*)d_in[1]; // [NUM_CODES, DIM] fp32
    float*       out      = (float*)d_out;         // [N, DIM] fp32

    (void)in_sizes; (void)n_in; (void)out_size;

    build_tangents<<<(NUM_CODES + 1 + 7) / 8, 256>>>(emb);
    visit_mean<<<NVISITS / 8, 256>>>(code_ids, out);
}

// round 4
// speedup vs baseline: 1.0559x; 1.0559x over previous
#include <cuda_runtime.h>
#include <cuda_fp16.h>
#include <cstdint>

#define NUM_CODES 100000
#define DIM 64
#define NVISITS 65536
#define LCODES 48

// fp16 pre-scaled tangent table + trailing ZERO row (index NUM_CODES) for
// masked slots. Row = 64 halfs = 128 B = one L2 line. ~12.8 MB, L2-resident.
__device__ __align__(16) __half2 g_tang[(size_t)(NUM_CODES + 1) * (DIM / 2)];

// ---------------------------------------------------------------------------
// Pass 1: tang[c] = (atanh(min(||emb_c||,1-1e-7)) / max(||emb_c||,1e-15)) * emb_c
// One warp per row; lane owns 2 dims. Butterfly norm reduce, Taylor atanh(x)/x
// in the small-norm regime (data: ||x|| ~ 0.008). Warp NUM_CODES zeroes pad row.
// ---------------------------------------------------------------------------
__global__ void __launch_bounds__(256) build_tangents(const float* __restrict__ emb) {
    int warp = (blockIdx.x * blockDim.x + threadIdx.x) >> 5;
    int lane = threadIdx.x & 31;
    if (warp > NUM_CODES) return;

    if (warp == NUM_CODES) {
        g_tang[(size_t)warp * (DIM / 2) + lane] = __half2half2(__ushort_as_half(0));
        return;
    }

    const float2 v = reinterpret_cast<const float2*>(emb + (size_t)warp * DIM)[lane];
    float ss = v.x * v.x + v.y * v.y;
    #pragma unroll
    for (int o = 16; o; o >>= 1)
        ss += __shfl_xor_sync(0xffffffffu, ss, o);

    float s;
    if (ss < 0.09f) {
        // atanh(x)/x = 1 + y/3 + y^2/5 + y^3/7 + y^4/9, y = x^2 = ss.
        s = 1.0f + ss * (0.33333334f + ss * (0.2f + ss * (0.14285715f + ss * 0.11111111f)));
    } else {
        float n = fmaxf(sqrtf(ss), 1e-15f);
        float a = fminf(n, 1.0f - 1e-7f);
        s = atanhf(a) / n;
    }

    g_tang[(size_t)warp * (DIM / 2) + lane] =
        __float22half2_rn(make_float2(s * v.x, s * v.y));
}

// half2 add on raw u32 payloads (HADD2).
__device__ __forceinline__ uint32_t hadd2u(uint32_t a, uint32_t b) {
    uint32_t r;
    asm("add.rn.f16x2 %0, %1, %2;" : "=r"(r) : "r"(a), "r"(b));
    return r;
}

// Convert one half2 to f32x2 and add into a packed f32x2 accumulator.
__device__ __forceinline__ void hacc2(uint32_t h2, unsigned long long& acc) {
    asm("{\n\t"
        ".reg .f16 l, h;\n\t"
        ".reg .f32 fl, fh;\n\t"
        ".reg .b64 fv;\n\t"
        "mov.b32 {l, h}, %1;\n\t"
        "cvt.f32.f16 fl, l;\n\t"
        "cvt.f32.f16 fh, h;\n\t"
        "mov.b64 fv, {fl, fh};\n\t"
        "add.rn.f32x2 %0, %0, fv;\n\t"
        "}" : "+l"(acc) : "r"(h2));
}

__device__ __forceinline__ void fadd2(float& x, float& y, float ox, float oy) {
    unsigned long long a, b;
    asm("mov.b64 %0, {%1, %2};" : "=l"(a) : "f"(x), "f"(y));
    asm("mov.b64 %0, {%1, %2};" : "=l"(b) : "f"(ox), "f"(oy));
    asm("add.rn.f32x2 %0, %0, %1;" : "+l"(a) : "l"(b));
    asm("mov.b64 {%0, %1}, %2;" : "=f"(x), "=f"(y) : "l"(a));
}

// ---------------------------------------------------------------------------
// Pass 2: out[visit] = mean over valid codes of tang[code].
// One warp per visit; quarter-warp (8 lanes x 16B) per fp16 row -> one LDG.128
// gathers FOUR rows; 12 gathers issued up-front (MLP 12). Accumulation is a
// two-level fp16 pairwise tree (HADD2) over groups of 4 gathers, converting
// only the 12 surviving half2 partials to fp32 -> 72 arith instr/warp vs 144.
// Masked slots hit the hot zero row; valid count via ballot+popc.
// ---------------------------------------------------------------------------
__global__ void __launch_bounds__(256, 4) visit_mean(const int* __restrict__ ids,
                                                     float* __restrict__ out) {
    int warp = (blockIdx.x * blockDim.x + threadIdx.x) >> 5;
    int lane = threadIdx.x & 31;
    if (warp >= NVISITS) return;

    const int quarter = lane >> 3;
    const int ql      = lane & 7;

    const int* __restrict__ vid = ids + (size_t)warp * LCODES;
    const int idA = __ldg(vid + lane);               // slots 0..31
    const int idB = __ldg(vid + 32 + (lane & 15));   // slots 32..47

    const int cnt = __popc(__ballot_sync(0xffffffffu, idA >= 0)) +
                    __popc(__ballot_sync(0xffffffffu, idB >= 0) & 0xffffu);

    const char* __restrict__ base = reinterpret_cast<const char*>(g_tang);

    // Issue all 12 gathers before consuming any.
    uint4 v[12];
    #pragma unroll
    for (int t = 0; t < 12; t++) {
        int slot = 4 * t + quarter;
        int id = (t < 8) ? __shfl_sync(0xffffffffu, idA, slot)
                         : __shfl_sync(0xffffffffu, idB, slot - 32);
        unsigned idx = (id >= 0) ? (unsigned)id : (unsigned)NUM_CODES;
        v[t] = *reinterpret_cast<const uint4*>(base + (size_t)idx * 128u + ql * 16);
    }

    // Two-level fp16 pairwise tree per group of 4 gathers, fp32 accumulate.
    unsigned long long acc[4] = {0ull, 0ull, 0ull, 0ull};
    #pragma unroll
    for (int g = 0; g < 3; g++) {
        const uint4& a = v[4 * g + 0];
        const uint4& b = v[4 * g + 1];
        const uint4& c = v[4 * g + 2];
        const uint4& d = v[4 * g + 3];
        hacc2(hadd2u(hadd2u(a.x, b.x), hadd2u(c.x, d.x)), acc[0]);
        hacc2(hadd2u(hadd2u(a.y, b.y), hadd2u(c.y, d.y)), acc[1]);
        hacc2(hadd2u(hadd2u(a.z, b.z), hadd2u(c.z, d.z)), acc[2]);
        hacc2(hadd2u(hadd2u(a.w, b.w), hadd2u(c.w, d.w)), acc[3]);
    }

    float f[8];
    #pragma unroll
    for (int j = 0; j < 4; j++) {
        f[2 * j]     = __uint_as_float((unsigned)(acc[j] & 0xffffffffull));
        f[2 * j + 1] = __uint_as_float((unsigned)(acc[j] >> 32));
    }

    // Combine four quarter-warp accumulators (packed adds).
    #pragma unroll
    for (int o = 16; o >= 8; o >>= 1) {
        float g[8];
        #pragma unroll
        for (int i = 0; i < 8; i++)
            g[i] = __shfl_down_sync(0xffffffffu, f[i], o);
        #pragma unroll
        for (int j = 0; j < 4; j++)
            fadd2(f[2 * j], f[2 * j + 1], g[2 * j], g[2 * j + 1]);
    }

    if (quarter == 0) {
        float inv = 1.0f / (float)(cnt > 1 ? cnt : 1);
        float4 o0 = make_float4(f[0] * inv, f[1] * inv, f[2] * inv, f[3] * inv);
        float4 o1 = make_float4(f[4] * inv, f[5] * inv, f[6] * inv, f[7] * inv);
        float4* op = reinterpret_cast<float4*>(out + (size_t)warp * DIM + ql * 8);
        op[0] = o0;
        op[1] = o1;
    }
}

extern "C" void kernel_launch(void* const* d_in, const int* in_sizes, int n_in,
                              void* d_out, int out_size) {
    const int*   code_ids = (const int*)d_in[0];   // [N, L] int32, -1 = pad
    const float* emb      = (const float*)d_in[1]; // [NUM_CODES, DIM] fp32
    float*       out      = (float*)d_out;         // [N, DIM] fp32

    (void)in_sizes; (void)n_in; (void)out_size;

    build_tangents<<<(NUM_CODES + 1 + 7) / 8, 256>>>(emb);
    visit_mean<<<NVISITS / 8, 256>>>(code_ids, out);
}